// round 17
// baseline (speedup 1.0000x reference)
#include <cuda_runtime.h>
#include <cuda_bf16.h>
#include <cstdint>

#define BATCH 256
#define D     512
#define HID   2048
#define SLOTS 32768
#define NSPLIT 32
#define NEG_INF (-1e30f)

typedef unsigned long long ull;

// ---------------- device scratch ----------------
__device__ float g_K[BATCH * D];
__device__ float g_V[BATCH * D];
__device__ float g_G[BATCH * BATCH];
__device__ float g_Gp[4 * BATCH * BATCH];
__device__ float g_Sb[(size_t)BATCH * SLOTS];
__device__ float g_c[BATCH];
__device__ float g_E[BATCH];
__device__ float g_t1v[BATCH];
__device__ float g_t2v[BATCH];
__device__ int   g_t1i[BATCH];
__device__ int   g_t2i[BATCH];
__device__ int   g_slot[BATCH];
__device__ int   g_death[BATCH];
__device__ float g_A1[BATCH * BATCH];
__device__ float g_A2[BATCH * BATCH];
__device__ float g_Rpart[(size_t)NSPLIT * BATCH * D];
__device__ float g_merged[BATCH * 2 * D];
__device__ float g_hidden[BATCH * HID];
__device__ float g_P2[4 * BATCH * D];
// 6-segment bf16 stacks for the score GEMM (24-bit mantissa product)
__device__ __nv_bfloat16 g_K6[(size_t)BATCH * 6 * D];
__device__ __nv_bfloat16 g_mk6[(size_t)SLOTS * 6 * D];

// ---------------- helpers ----------------
__device__ __forceinline__ uint32_t smem_u32(const void* p) {
    uint32_t a;
    asm("{ .reg .u64 t; cvta.to.shared.u64 t, %1; cvt.u32.u64 %0, t; }" : "=r"(a) : "l"(p));
    return a;
}
__device__ __forceinline__ void ldsm4(uint32_t& r0, uint32_t& r1, uint32_t& r2,
                                      uint32_t& r3, uint32_t a) {
    asm volatile("ldmatrix.sync.aligned.m8n8.x4.shared.b16 {%0,%1,%2,%3}, [%4];"
                 : "=r"(r0), "=r"(r1), "=r"(r2), "=r"(r3) : "r"(a));
}
__device__ __forceinline__ void mma16816(float* c, const uint32_t* a, const uint32_t* b) {
    asm volatile(
        "mma.sync.aligned.m16n8k16.row.col.f32.bf16.bf16.f32 "
        "{%0,%1,%2,%3}, {%4,%5,%6,%7}, {%8,%9}, {%0,%1,%2,%3};"
        : "+f"(c[0]), "+f"(c[1]), "+f"(c[2]), "+f"(c[3])
        : "r"(a[0]), "r"(a[1]), "r"(a[2]), "r"(a[3]), "r"(b[0]), "r"(b[1]));
}
// f32x2 packed helpers (R2-proven)
__device__ __forceinline__ void fma2(ull& d, ull a, ull b) {
    asm("fma.rn.f32x2 %0, %1, %2, %0;" : "+l"(d) : "l"(a), "l"(b));
}
__device__ __forceinline__ ull dup2(float x) {
    ull r; asm("mov.b64 %0, {%1, %1};" : "=l"(r) : "f"(x)); return r;
}
__device__ __forceinline__ ull pk2(float lo, float hi) {
    ull r; asm("mov.b64 %0, {%1, %2};" : "=l"(r) : "f"(lo), "f"(hi)); return r;
}
__device__ __forceinline__ void upk2(ull v, float& lo, float& hi) {
    asm("mov.b64 {%0, %1}, %2;" : "=f"(lo), "=f"(hi) : "l"(v));
}

// ---- 3-component split: src[R,K] f32 -> dst[R,6K] (24-bit score GEMM).
// pat0 (A): h1,h2,h1,h3,h1,h2   pat1 (B): h1,h1,h2,h1,h3,h2
__global__ __launch_bounds__(256) void split6(
    const float* __restrict__ src, __nv_bfloat16* __restrict__ dst,
    int K, int pat, int total2)
{
    int idx = blockIdx.x * 256 + threadIdx.x;
    if (idx >= total2) return;
    const int kh = K >> 1;
    int row = idx / kh;
    int cp = (idx - row * kh) << 1;
    float2 v = ((const float2*)src)[idx];
    __nv_bfloat16 a1 = __float2bfloat16_rn(v.x);
    __nv_bfloat16 b1 = __float2bfloat16_rn(v.y);
    float ra = v.x - __bfloat162float(a1);
    float rb = v.y - __bfloat162float(b1);
    __nv_bfloat16 a2 = __float2bfloat16_rn(ra);
    __nv_bfloat16 b2 = __float2bfloat16_rn(rb);
    float ra2 = ra - __bfloat162float(a2);
    float rb2 = rb - __bfloat162float(b2);
    __nv_bfloat162 p1; p1.x = a1; p1.y = b1;
    __nv_bfloat162 p2; p2.x = a2; p2.y = b2;
    __nv_bfloat162 p3;
    p3.x = __float2bfloat16_rn(ra2);
    p3.y = __float2bfloat16_rn(rb2);
    size_t base = (size_t)row * (6 * (size_t)K) + cp;
    if (pat == 0) {
        *(__nv_bfloat162*)(dst + base) = p1;
        *(__nv_bfloat162*)(dst + base + K) = p2;
        *(__nv_bfloat162*)(dst + base + 2 * (size_t)K) = p1;
        *(__nv_bfloat162*)(dst + base + 3 * (size_t)K) = p3;
        *(__nv_bfloat162*)(dst + base + 4 * (size_t)K) = p1;
        *(__nv_bfloat162*)(dst + base + 5 * (size_t)K) = p2;
    } else {
        *(__nv_bfloat162*)(dst + base) = p1;
        *(__nv_bfloat162*)(dst + base + K) = p1;
        *(__nv_bfloat162*)(dst + base + 2 * (size_t)K) = p2;
        *(__nv_bfloat162*)(dst + base + 3 * (size_t)K) = p1;
        *(__nv_bfloat162*)(dst + base + 4 * (size_t)K) = p3;
        *(__nv_bfloat162*)(dst + base + 5 * (size_t)K) = p2;
    }
}

// =======================================================================
// bf16 HMMA NT GEMM on stacked operands (score GEMM only).
// =======================================================================
#define SMS 40

__global__ __launch_bounds__(256) void hgemm_bf16(
    const __nv_bfloat16* __restrict__ A, const __nv_bfloat16* __restrict__ B,
    float* __restrict__ C, int M, int N, int Keff, int lda, int ldb)
{
    __shared__ __align__(16) __nv_bfloat16 sA[128 * SMS];
    __shared__ __align__(16) __nv_bfloat16 sB[128 * SMS];

    const int t = threadIdx.x;
    const int lane = t & 31, wid = t >> 5;
    const int bm = blockIdx.y * 128, bn = blockIdx.x * 128;
    const int nch = Keff >> 5;

    const int lr = t >> 1, lh = (t & 1) << 4;
    const __nv_bfloat16* Ab = A + (size_t)(bm + lr) * lda + lh;
    const __nv_bfloat16* Bb = B + (size_t)(bn + lr) * ldb + lh;

    const int wm = (wid >> 2) * 64;
    const int wn = (wid & 3) * 32;
    const uint32_t sAA = smem_u32(sA), sBA = smem_u32(sB);
    const uint32_t sOff = (uint32_t)(lr * SMS + lh) * 2;

    float acc[4][4][4];
#pragma unroll
    for (int im = 0; im < 4; im++)
#pragma unroll
        for (int jn = 0; jn < 4; jn++)
#pragma unroll
            for (int q = 0; q < 4; q++) acc[im][jn][q] = 0.f;

    for (int ch = 0; ch < nch; ch++) {
        uint4 va0 = *(const uint4*)(Ab + ch * 32);
        uint4 va1 = *(const uint4*)(Ab + ch * 32 + 8);
        uint4 vb0 = *(const uint4*)(Bb + ch * 32);
        uint4 vb1 = *(const uint4*)(Bb + ch * 32 + 8);
        __syncthreads();
        *(uint4*)((char*)sA + sOff) = va0;
        *(uint4*)((char*)sA + sOff + 16) = va1;
        *(uint4*)((char*)sB + sOff) = vb0;
        *(uint4*)((char*)sB + sOff + 16) = vb1;
        __syncthreads();

#pragma unroll
        for (int k0 = 0; k0 < 32; k0 += 16) {
            uint32_t a[4][4], b[4][2];
#pragma unroll
            for (int im = 0; im < 4; im++) {
                uint32_t off =
                    ((uint32_t)((wm + im * 16 + (lane & 15)) * SMS + k0 +
                                ((lane >> 4) << 3))) << 1;
                ldsm4(a[im][0], a[im][1], a[im][2], a[im][3], sAA + off);
            }
#pragma unroll
            for (int g = 0; g < 2; g++) {
                uint32_t row = wn + g * 16 + (((lane >> 3) & 1) << 3) + (lane & 7);
                uint32_t off =
                    ((uint32_t)(row * SMS + k0 + ((lane >> 4) << 3))) << 1;
                uint32_t r0, r1, r2, r3;
                ldsm4(r0, r1, r2, r3, sBA + off);
                b[2 * g][0] = r0; b[2 * g + 1][0] = r1;
                b[2 * g][1] = r2; b[2 * g + 1][1] = r3;
            }
#pragma unroll
            for (int im = 0; im < 4; im++)
#pragma unroll
                for (int jn = 0; jn < 4; jn++)
                    mma16816(acc[im][jn], a[im], b[jn]);
        }
    }

#pragma unroll
    for (int im = 0; im < 4; im++) {
#pragma unroll
        for (int jn = 0; jn < 4; jn++) {
            int r0 = bm + wm + im * 16 + (lane >> 2);
            int c0 = bn + wn + jn * 8 + ((lane & 3) << 1);
            float2 v0; v0.x = acc[im][jn][0]; v0.y = acc[im][jn][1];
            float2 v1; v1.x = acc[im][jn][2]; v1.y = acc[im][jn][3];
            *(float2*)&C[(size_t)r0 * N + c0] = v0;
            *(float2*)&C[(size_t)(r0 + 8) * N + c0] = v1;
        }
    }
}

// =======================================================================
// f32x2 128x128x16 NN split-K GEMM (R2-proven): Cpart[z] = A[:,chunk]@B[chunk,:]
// =======================================================================
__global__ __launch_bounds__(256) void gemm_nn128_splitk(
    const float* __restrict__ A, const float* __restrict__ B,
    float* __restrict__ Cpart, int M, int N, int Ktot)
{
    __shared__ float As[2][16][132];
    __shared__ float Bs[2][16][132];
    const int bm = blockIdx.y * 128, bn = blockIdx.x * 128;
    const int tid = threadIdx.x;
    const int tm = (tid >> 4) << 3, tn = (tid & 15) << 3;
    const int lr = tid >> 2, lc = (tid & 3) << 2;
    const int brow = tid >> 5, bcol = (tid & 31) << 2;
    const int chunk = Ktot / gridDim.z;
    const int kbeg = blockIdx.z * chunk;
    const int nt = chunk >> 4;

    const float* Ap0 = A + (size_t)(bm + lr) * Ktot + kbeg + lc;
    const float* Ap1 = A + (size_t)(bm + lr + 64) * Ktot + kbeg + lc;
    const float* Bp0 = B + (size_t)(kbeg + brow) * N + bn + bcol;
    const float* Bp1 = B + (size_t)(kbeg + brow + 8) * N + bn + bcol;

    ull acc[8][4];
#pragma unroll
    for (int r = 0; r < 8; r++)
#pragma unroll
        for (int c = 0; c < 4; c++) acc[r][c] = 0ull;

    float4 ra0 = *(const float4*)Ap0;
    float4 ra1 = *(const float4*)Ap1;
    float4 rb0 = *(const float4*)Bp0;
    float4 rb1 = *(const float4*)Bp1;

#define NN_STS(b)                                                              \
    As[b][lc + 0][lr] = ra0.x; As[b][lc + 1][lr] = ra0.y;                      \
    As[b][lc + 2][lr] = ra0.z; As[b][lc + 3][lr] = ra0.w;                      \
    As[b][lc + 0][lr + 64] = ra1.x; As[b][lc + 1][lr + 64] = ra1.y;            \
    As[b][lc + 2][lr + 64] = ra1.z; As[b][lc + 3][lr + 64] = ra1.w;            \
    *(float4*)&Bs[b][brow][bcol] = rb0;                                        \
    *(float4*)&Bs[b][brow + 8][bcol] = rb1;

    NN_STS(0)
    __syncthreads();

    for (int t = 0; t < nt; t++) {
        const int cur = t & 1;
        if (t + 1 < nt) {
            const int ko = (t + 1) << 4;
            ra0 = *(const float4*)(Ap0 + ko);
            ra1 = *(const float4*)(Ap1 + ko);
            rb0 = *(const float4*)(Bp0 + (size_t)ko * N);
            rb1 = *(const float4*)(Bp1 + (size_t)ko * N);
        }
#pragma unroll
        for (int kk = 0; kk < 16; kk++) {
            float4 a0 = *(const float4*)&As[cur][kk][tm];
            float4 a1 = *(const float4*)&As[cur][kk][tm + 4];
            float4 b0 = *(const float4*)&Bs[cur][kk][tn];
            float4 b1 = *(const float4*)&Bs[cur][kk][tn + 4];
            ull bb0 = pk2(b0.x, b0.y), bb1 = pk2(b0.z, b0.w);
            ull bb2 = pk2(b1.x, b1.y), bb3 = pk2(b1.z, b1.w);
            float av[8] = {a0.x, a0.y, a0.z, a0.w, a1.x, a1.y, a1.z, a1.w};
#pragma unroll
            for (int r = 0; r < 8; r++) {
                ull aa = dup2(av[r]);
                fma2(acc[r][0], aa, bb0); fma2(acc[r][1], aa, bb1);
                fma2(acc[r][2], aa, bb2); fma2(acc[r][3], aa, bb3);
            }
        }
        if (t + 1 < nt) {
            const int nb = 1 - cur;
            NN_STS(nb)
        }
        __syncthreads();
    }
#undef NN_STS

    float* Cp = Cpart + (size_t)blockIdx.z * M * N;
#pragma unroll
    for (int r = 0; r < 8; r++) {
        const size_t row = bm + tm + r;
        float4 o0, o1;
        upk2(acc[r][0], o0.x, o0.y); upk2(acc[r][1], o0.z, o0.w);
        upk2(acc[r][2], o1.x, o1.y); upk2(acc[r][3], o1.z, o1.w);
        *(float4*)&Cp[row * N + bn + tn] = o0;
        *(float4*)&Cp[row * N + bn + tn + 4] = o1;
    }
}

// ================= 64x64 NT fp32 GEMM (proj / Gram / MLP) =================
__device__ __forceinline__ void gemm64_body(
    const float* __restrict__ A, const float* __restrict__ B,
    const float* __restrict__ bias, float* __restrict__ C,
    int M, int N, int K, int kbeg, int kend, int relu)
{
    __shared__ float As[16][64];
    __shared__ float Bs[16][64];
    const int bm = blockIdx.y * 64;
    const int bn = blockIdx.x * 64;
    const int tid = threadIdx.x;
    const int tm = (tid >> 4) << 2;
    const int tn = (tid & 15) << 2;
    const int lr = tid >> 2;
    const int lc = (tid & 3) << 2;
    float acc[4][4];
#pragma unroll
    for (int r = 0; r < 4; r++)
#pragma unroll
        for (int c = 0; c < 4; c++) acc[r][c] = 0.f;

    const float* Ap = A + (size_t)(bm + lr) * K + lc;
    const float* Bp = B + (size_t)(bn + lr) * K + lc;
    for (int k0 = kbeg; k0 < kend; k0 += 16) {
        float4 a4 = *(const float4*)(Ap + k0);
        float4 b4 = *(const float4*)(Bp + k0);
        As[lc + 0][lr] = a4.x; As[lc + 1][lr] = a4.y;
        As[lc + 2][lr] = a4.z; As[lc + 3][lr] = a4.w;
        Bs[lc + 0][lr] = b4.x; Bs[lc + 1][lr] = b4.y;
        Bs[lc + 2][lr] = b4.z; Bs[lc + 3][lr] = b4.w;
        __syncthreads();
#pragma unroll
        for (int kk = 0; kk < 16; kk++) {
            float4 av = *(const float4*)&As[kk][tm];
            float4 bv = *(const float4*)&Bs[kk][tn];
            float a[4] = {av.x, av.y, av.z, av.w};
            float b[4] = {bv.x, bv.y, bv.z, bv.w};
#pragma unroll
            for (int r = 0; r < 4; r++)
#pragma unroll
                for (int c = 0; c < 4; c++)
                    acc[r][c] = fmaf(a[r], b[c], acc[r][c]);
        }
        __syncthreads();
    }
#pragma unroll
    for (int r = 0; r < 4; r++) {
        int row = bm + tm + r;
#pragma unroll
        for (int c = 0; c < 4; c++) {
            int col = bn + tn + c;
            float v = acc[r][c];
            if (bias) v += bias[col];
            if (relu) v = fmaxf(v, 0.f);
            C[(size_t)row * N + col] = v;
        }
    }
}

__global__ __launch_bounds__(256) void proj_kernel(
    const float* __restrict__ S,
    const float* __restrict__ Wk, const float* __restrict__ bk,
    const float* __restrict__ Wv, const float* __restrict__ bv)
{
    if (blockIdx.z == 0)
        gemm64_body(S, Wk, bk, g_K, BATCH, D, D, 0, D, 0);
    else
        gemm64_body(S, Wv, bv, g_V, BATCH, D, D, 0, D, 0);
}

__global__ __launch_bounds__(256) void gemm_nt64(
    const float* __restrict__ A, const float* __restrict__ B,
    const float* __restrict__ bias, float* __restrict__ C,
    int M, int N, int K, int relu)
{
    gemm64_body(A, B, bias, C, M, N, K, 0, K, relu);
}

__global__ __launch_bounds__(256) void gemm_nt64_splitk(
    const float* __restrict__ A, const float* __restrict__ B,
    float* __restrict__ Cpart, int M, int N, int K)
{
    const int chunk = K / gridDim.z;
    const int kbeg = blockIdx.z * chunk;
    gemm64_body(A, B, nullptr, Cpart + (size_t)blockIdx.z * M * N,
                M, N, K, kbeg, kbeg + chunk, 0);
}

__global__ __launch_bounds__(256) void reduce_add(
    const float* __restrict__ part, const float* __restrict__ bias,
    float* __restrict__ out, int total, int N, int nz, int relu)
{
    int idx = blockIdx.x * 256 + threadIdx.x;
    if (idx >= total) return;
    float s = bias ? bias[idx % N] : 0.f;
    for (int z = 0; z < nz; z++) s += part[(size_t)z * total + idx];
    if (relu) s = fmaxf(s, 0.f);
    out[idx] = s;
}

// ---- per-row max / top-2 / exp-in-place / sumexp ----
__global__ __launch_bounds__(256) void rowstat()
{
    const int i = blockIdx.x;
    const int t = threadIdx.x;
    float* row = g_Sb + (size_t)i * SLOTS;

    float v1 = NEG_INF; int i1 = -1;
    float v2 = NEG_INF; int i2 = -1;
    for (int s = t; s < SLOTS; s += 256) {
        float v = row[s];
        if (v > v1) { v2 = v1; i2 = i1; v1 = v; i1 = s; }
        else if (v > v2) { v2 = v; i2 = s; }
    }
    __shared__ float sv1[256], sv2[256];
    __shared__ int   si1[256], si2[256];
    sv1[t] = v1; si1[t] = i1; sv2[t] = v2; si2[t] = i2;
    __syncthreads();
    for (int off = 128; off > 0; off >>= 1) {
        if (t < off) {
            float b1 = sv1[t + off], b2 = sv2[t + off];
            int bi1 = si1[t + off], bi2 = si2[t + off];
            float a1 = sv1[t], a2 = sv2[t];
            int ai1 = si1[t], ai2 = si2[t];
            float n1, n2; int ni1, ni2;
            if (b1 > a1 || (b1 == a1 && bi1 < ai1)) {
                n1 = b1; ni1 = bi1;
                if (a1 > b2 || (a1 == b2 && ai1 < bi2)) { n2 = a1; ni2 = ai1; }
                else { n2 = b2; ni2 = bi2; }
            } else {
                n1 = a1; ni1 = ai1;
                if (b1 > a2 || (b1 == a2 && bi1 < ai2)) { n2 = b1; ni2 = bi1; }
                else { n2 = a2; ni2 = ai2; }
            }
            sv1[t] = n1; si1[t] = ni1; sv2[t] = n2; si2[t] = ni2;
        }
        __syncthreads();
    }
    __shared__ float cmax;
    if (t == 0) {
        cmax = sv1[0];
        g_c[i] = sv1[0];
        g_t1v[i] = sv1[0]; g_t1i[i] = si1[0];
        g_t2v[i] = sv2[0]; g_t2i[i] = si2[0];
    }
    __syncthreads();
    const float cm = cmax;
    float sum = 0.f;
    for (int s = t; s < SLOTS; s += 256) {
        float p = __expf(row[s] - cm);
        row[s] = p;
        sum += p;
    }
    sv1[t] = sum;
    __syncthreads();
    for (int off = 128; off > 0; off >>= 1) {
        if (t < off) sv1[t] += sv1[t + off];
        __syncthreads();
    }
    if (t == 0) g_E[i] = sv1[0];
}

// ---- exact fp32 rescore of top-2 candidates ----
__global__ __launch_bounds__(256) void rescore(const float* __restrict__ mk)
{
    const int i = blockIdx.x;
    const int t = threadIdx.x;
    const int cand = t >> 7;
    const int lt = t & 127;
    const int slot = cand ? g_t2i[i] : g_t1i[i];
    const float* krow = g_K + i * D;
    const float* mrow = mk + (size_t)slot * D;
    float s = 0.f;
    for (int d = lt; d < D; d += 128) s = fmaf(krow[d], mrow[d], s);
    __shared__ float red[256];
    red[t] = s;
    __syncthreads();
    for (int off = 64; off > 0; off >>= 1) {
        if (lt < off) red[t] += red[t + off];
        __syncthreads();
    }
    if (lt == 0) {
        if (cand == 0) g_t1v[i] = red[t];
        else g_t2v[i] = red[t];
    }
}

// ---- sequential slot-chain resolution ----
__global__ __launch_bounds__(256) void seq_kernel()
{
    __shared__ unsigned bm_[SLOTS / 32];
    __shared__ int slotS[256];
    __shared__ int deathS[256];
    __shared__ unsigned char liveF[256];
    __shared__ float rV[8]; __shared__ int rJ[8];
    __shared__ float s_wv; __shared__ int s_wj;
    __shared__ float s_bv; __shared__ int s_bs;
    __shared__ int s_fall, s_prev, s_slot;

    const int t = threadIdx.x;
    for (int w = t; w < SLOTS / 32; w += 256) bm_[w] = 0u;
    liveF[t] = 0; deathS[t] = 1 << 30; slotS[t] = -1;
    __syncthreads();

    for (int i = 0; i < BATCH; i++) {
        float v = NEG_INF; int jj = -1;
        if (t < i && liveF[t]) { v = g_G[i * BATCH + t]; jj = t; }
        for (int off = 16; off; off >>= 1) {
            float ov = __shfl_down_sync(0xffffffffu, v, off);
            int   oj = __shfl_down_sync(0xffffffffu, jj, off);
            bool take = false;
            if (oj >= 0) {
                if (jj < 0) take = true;
                else if (ov > v) take = true;
                else if (ov == v && slotS[oj] < slotS[jj]) take = true;
            }
            if (take) { v = ov; jj = oj; }
        }
        if ((t & 31) == 0) { rV[t >> 5] = v; rJ[t >> 5] = jj; }
        __syncthreads();
        if (t == 0) {
            float bv = rV[0]; int bj = rJ[0];
            for (int w = 1; w < 8; w++) {
                float ov = rV[w]; int oj = rJ[w];
                bool take = false;
                if (oj >= 0) {
                    if (bj < 0) take = true;
                    else if (ov > bv) take = true;
                    else if (ov == bv && slotS[oj] < slotS[bj]) take = true;
                }
                if (take) { bv = ov; bj = oj; }
            }
            s_wv = bv; s_wj = bj;
            s_fall = 0; s_prev = -1;
            int b1 = g_t1i[i];
            if (!((bm_[b1 >> 5] >> (b1 & 31)) & 1u)) { s_bs = b1; s_bv = g_t1v[i]; }
            else {
                int b2 = g_t2i[i];
                if (!((bm_[b2 >> 5] >> (b2 & 31)) & 1u)) { s_bs = b2; s_bv = g_t2v[i]; }
                else s_fall = 1;
            }
        }
        __syncthreads();
        if (s_fall) {
            const float* Prow = g_Sb + (size_t)i * SLOTS;
            float fv = NEG_INF; int fs = -1;
            for (int s = t; s < SLOTS; s += 256) {
                if (!((bm_[s >> 5] >> (s & 31)) & 1u)) {
                    float p = Prow[s];
                    if (p > fv) { fv = p; fs = s; }
                }
            }
            for (int off = 16; off; off >>= 1) {
                float ov = __shfl_down_sync(0xffffffffu, fv, off);
                int   os = __shfl_down_sync(0xffffffffu, fs, off);
                if (os >= 0 && (fs < 0 || ov > fv || (ov == fv && os < fs))) { fv = ov; fs = os; }
            }
            if ((t & 31) == 0) { rV[t >> 5] = fv; rJ[t >> 5] = fs; }
            __syncthreads();
            if (t == 0) {
                float bv2 = rV[0]; int bs2 = rJ[0];
                for (int w = 1; w < 8; w++) {
                    if (rJ[w] >= 0 && (bs2 < 0 || rV[w] > bv2 ||
                        (rV[w] == bv2 && rJ[w] < bs2))) { bv2 = rV[w]; bs2 = rJ[w]; }
                }
                s_bs = bs2;
                s_bv = __logf(bv2) + g_c[i];
            }
            __syncthreads();
        }
        if (t == 0) {
            float bestv = s_bv; int bests = s_bs;
            if (s_wj >= 0) {
                float wv = s_wv; int wslot = slotS[s_wj];
                if (wv > bestv || (wv == bestv && wslot < bests)) { bestv = wv; bests = wslot; }
            }
            s_slot = bests;
        }
        __syncthreads();
        if (t < i && liveF[t] && slotS[t] == s_slot) s_prev = t;
        __syncthreads();
        if (t == 0) {
            if (s_prev >= 0) { liveF[s_prev] = 0; deathS[s_prev] = i; }
            bm_[s_slot >> 5] |= (1u << (s_slot & 31));
            slotS[i] = s_slot; liveF[i] = 1;
            g_slot[i] = s_slot;
        }
        __syncthreads();
    }
    g_death[t] = deathS[t];
}

__global__ __launch_bounds__(256) void abuild()
{
    const int i = blockIdx.x;
    const int j = threadIdx.x;
    const bool live = (j < i) && (i <= g_death[j]);
    g_A1[i * BATCH + j] = live ? __expf(g_G[i * BATCH + j] - g_c[i]) : 0.f;
    g_A2[i * BATCH + j] = live ? g_Sb[(size_t)i * SLOTS + g_slot[j]] : 0.f;
}

__global__ __launch_bounds__(512) void copyS(const float* __restrict__ S)
{
    const int i = blockIdx.x;
    const int t = threadIdx.x;
    g_merged[i * 2 * D + t] = S[(size_t)i * D + t];
}

__global__ __launch_bounds__(512) void readfin(const float* __restrict__ mem_vals)
{
    const int i = blockIdx.x;
    const int t = threadIdx.x;
    __shared__ float a1[256], a2[256];
    __shared__ int sl[256];
    __shared__ float zsh;
    if (t < 256) {
        a1[t] = g_A1[i * BATCH + t];
        a2[t] = g_A2[i * BATCH + t];
        sl[t] = g_slot[t];
    }
    __syncthreads();
    if (t == 0) {
        float Z = g_E[i];
        for (int j = 0; j < BATCH; j++) Z += a1[j] - a2[j];
        zsh = Z;
    }
    __syncthreads();
    float acc = 0.f;
#pragma unroll
    for (int p = 0; p < NSPLIT; p++)
        acc += g_Rpart[((size_t)p * BATCH + i) * D + t];
    for (int j = 0; j < i; j++) {
        float w1 = a1[j], w2 = a2[j];
        if (w1 != 0.f || w2 != 0.f)
            acc += w1 * g_V[j * D + t] - w2 * mem_vals[(size_t)sl[j] * D + t];
    }
    g_merged[i * 2 * D + D + t] = acc / zsh;
}

// ---------------- host launch ----------------
extern "C" void kernel_launch(void* const* d_in, const int* in_sizes, int n_in,
                              void* d_out, int out_size)
{
    const float* S  = (const float*)d_in[0];
    const float* mk = (const float*)d_in[1];
    const float* mv = (const float*)d_in[2];
    const float* Wk = (const float*)d_in[3];
    const float* bk = (const float*)d_in[4];
    const float* Wv = (const float*)d_in[5];
    const float* bv = (const float*)d_in[6];
    const float* W1 = (const float*)d_in[7];
    const float* b1 = (const float*)d_in[8];
    const float* W2 = (const float*)d_in[9];
    const float* b2 = (const float*)d_in[10];
    float* out = (float*)d_out;
    (void)in_sizes; (void)n_in; (void)out_size;

    void *pK, *pSb, *pRp, *pM, *pH, *pG, *pGp, *pP2, *pK6, *pmk6;
    cudaGetSymbolAddress(&pK,  g_K);
    cudaGetSymbolAddress(&pSb, g_Sb);
    cudaGetSymbolAddress(&pRp, g_Rpart);
    cudaGetSymbolAddress(&pM,  g_merged);
    cudaGetSymbolAddress(&pH,  g_hidden);
    cudaGetSymbolAddress(&pG,  g_G);
    cudaGetSymbolAddress(&pGp, g_Gp);
    cudaGetSymbolAddress(&pP2, g_P2);
    cudaGetSymbolAddress(&pK6, g_K6);
    cudaGetSymbolAddress(&pmk6, g_mk6);

    const dim3 t256(256);

    // projections (fp32 exact)
    proj_kernel<<<dim3(D / 64, BATCH / 64, 2), t256>>>(S, Wk, bk, Wv, bv);
    // 24-bit stacked splits of K and mem_keys (score GEMM operands)
    split6<<<(BATCH * D / 2 + 255) / 256, t256>>>(
        (const float*)pK, (__nv_bfloat16*)pK6, D, 0, BATCH * D / 2);
    split6<<<(SLOTS * D / 2 + 255) / 256, t256>>>(
        mk, (__nv_bfloat16*)pmk6, D, 1, SLOTS * D / 2);
    // Gram (fp32 exact)
    gemm_nt64_splitk<<<dim3(BATCH / 64, BATCH / 64, 4), t256>>>(
        (const float*)pK, (const float*)pK, (float*)pGp, BATCH, BATCH, D);
    reduce_add<<<(BATCH * BATCH) / 256, t256>>>(
        (const float*)pGp, nullptr, (float*)pG, BATCH * BATCH, BATCH, 4, 0);
    // Sb = K @ mk^T, HMMA 6-term stacked (24-bit mantissa grade)
    hgemm_bf16<<<dim3(SLOTS / 128, BATCH / 128), t256>>>(
        (const __nv_bfloat16*)pK6, (const __nv_bfloat16*)pmk6,
        (float*)pSb, BATCH, SLOTS, 6 * D, 6 * D, 6 * D);
    // softmax stats + exact rescore of argmax candidates
    rowstat<<<BATCH, 256>>>();
    rescore<<<BATCH, 256>>>(mk);
    // R = P @ mem_vals — EXACT fp32 (R2-proven f32x2 split-K NN GEMM)
    gemm_nn128_splitk<<<dim3(D / 128, BATCH / 128, NSPLIT), t256>>>(
        (const float*)pSb, mv, (float*)pRp, BATCH, D, SLOTS);
    // slot chain + corrections
    seq_kernel<<<1, 256>>>();
    abuild<<<BATCH, 256>>>();
    copyS<<<BATCH, 512>>>(S);
    readfin<<<BATCH, 512>>>(mv);
    // MLP — fp32 (R2-proven)
    gemm_nt64<<<dim3(HID / 64, BATCH / 64), t256>>>(
        (const float*)pM, W1, b1, (float*)pH, BATCH, HID, 2 * D, 1);
    gemm_nt64_splitk<<<dim3(D / 64, BATCH / 64, 4), t256>>>(
        (const float*)pH, W2, (float*)pP2, BATCH, D, HID);
    reduce_add<<<(BATCH * D) / 256, t256>>>(
        (const float*)pP2, b2, out, BATCH * D, D, 4, 0);
}